// round 5
// baseline (speedup 1.0000x reference)
#include <cuda_runtime.h>
#include <cstdint>

#define IMG_H 256
#define IMG_W 256
#define NFILT 64
#define NBATCH 32

__device__ __forceinline__ uint64_t pack2(float lo, float hi) {
    uint64_t r;
    asm("mov.b64 %0, {%1, %2};" : "=l"(r) : "f"(lo), "f"(hi));
    return r;
}
__device__ __forceinline__ void unpack2(uint64_t v, float& lo, float& hi) {
    asm("mov.b64 {%0, %1}, %2;" : "=f"(lo), "=f"(hi) : "l"(v));
}
__device__ __forceinline__ uint64_t ffma2(uint64_t a, uint64_t b, uint64_t c) {
    uint64_t d;
    asm("fma.rn.f32x2 %0, %1, %2, %3;" : "=l"(d) : "l"(a), "l"(b), "l"(c));
    return d;
}

// Each block: batch b, 4 consecutive rows, all 256 cols, all 64 filters.
// Each thread: one float4 (4 consecutive x) for all 64 filters.
// Accumulation via packed fma.rn.f32x2 (2 fp32 FMAs per instruction).
__global__ __launch_bounds__(256, 4) void spiking_conv_kernel(
    const float* __restrict__ tj,     // (32,1,256,256)
    const float* __restrict__ kern,   // (64,1,3,3)
    const float* __restrict__ Bv,     // (64,1)
    const float* __restrict__ D_i,    // (9,64), only row 0 used
    float* __restrict__ out)          // (32,64,256,256)
{
    __shared__ uint64_t ws2[NFILT * 9];   // duplicated weight pairs {w,w}
    __shared__ uint64_t sb2[NFILT];       // duplicated fused bias {bc,bc}

    const int tid = threadIdx.x;
    for (int i = tid; i < NFILT * 9; i += 256) {
        const float w = kern[i];
        ws2[i] = pack2(w, w);
    }
    if (tid < NFILT) {
        // threshold = 1 - D_i[0,f]; ti = conv + threshold - B[f]; clamp at 1
        const float bc = 1.0f - D_i[tid] - Bv[tid];
        sb2[tid] = pack2(bc, bc);
    }
    __syncthreads();

    const int b  = blockIdx.x >> 6;        // blockIdx / 64
    const int rg = blockIdx.x & 63;        // row-group
    const int y  = rg * 4 + (tid >> 6);    // output row
    const int x0 = (tid & 63) << 2;        // first of 4 output cols

    const float* img = tj + (size_t)b * IMG_H * IMG_W;

    // 3x6 input patch (zero pad == t_min pad since t_min = 0),
    // packed into 5 overlapping f32x2 pairs per row:
    //   p[r][c] = (in[r][c], in[r][c+1]),  c = 0..4
    uint64_t p[3][5];
#pragma unroll
    for (int r = 0; r < 3; r++) {
        const int yy = y - 1 + r;
        if (yy >= 0 && yy < IMG_H) {
            const float* row = img + yy * IMG_W;
            float i0 = (x0 > 0) ? __ldg(row + x0 - 1) : 0.0f;
            float4 m = *reinterpret_cast<const float4*>(row + x0);
            float i5 = (x0 + 4 < IMG_W) ? __ldg(row + x0 + 4) : 0.0f;
            p[r][0] = pack2(i0,  m.x);
            p[r][1] = pack2(m.x, m.y);
            p[r][2] = pack2(m.y, m.z);
            p[r][3] = pack2(m.z, m.w);
            p[r][4] = pack2(m.w, i5);
        } else {
#pragma unroll
            for (int c = 0; c < 5; c++) p[r][c] = 0ull;
        }
    }

    float* po = out + (size_t)b * NFILT * IMG_H * IMG_W
                    + (size_t)y * IMG_W + x0;

#pragma unroll 4
    for (int f = 0; f < NFILT; f++) {
        const uint64_t* w = &ws2[f * 9];
        uint64_t acc01 = sb2[f];
        uint64_t acc23 = acc01;
#pragma unroll
        for (int r = 0; r < 3; r++) {
#pragma unroll
            for (int c = 0; c < 3; c++) {
                const uint64_t wv2 = w[r * 3 + c];
                acc01 = ffma2(wv2, p[r][c],     acc01);
                acc23 = ffma2(wv2, p[r][c + 2], acc23);
            }
        }
        float a0, a1, a2, a3;
        unpack2(acc01, a0, a1);
        unpack2(acc23, a2, a3);
        float4 acc;
        acc.x = fminf(a0, 1.0f);
        acc.y = fminf(a1, 1.0f);
        acc.z = fminf(a2, 1.0f);
        acc.w = fminf(a3, 1.0f);
        *reinterpret_cast<float4*>(po + (size_t)f * IMG_H * IMG_W) = acc;
    }
}

extern "C" void kernel_launch(void* const* d_in, const int* in_sizes, int n_in,
                              void* d_out, int out_size) {
    const float* tj   = (const float*)d_in[0];  // 32*1*256*256
    const float* kern = (const float*)d_in[1];  // 64*1*3*3
    const float* Bv   = (const float*)d_in[2];  // 64*1
    const float* D_i  = (const float*)d_in[3];  // 9*64
    float* out = (float*)d_out;                 // 32*64*256*256

    spiking_conv_kernel<<<NBATCH * 64, 256>>>(tj, kern, Bv, D_i, out);
}